// round 6
// baseline (speedup 1.0000x reference)
#include <cuda_runtime.h>
#include <stdint.h>

// Vectorized bias init: out[i] = Param_b[b_params[i]], 4 per thread.
__global__ void bias_init_kernel(const float* __restrict__ Param_b,
                                 const int4* __restrict__ b_params4,
                                 float4* __restrict__ out4, int n4) {
    int i = blockIdx.x * blockDim.x + threadIdx.x;
    if (i < n4) {
        int4 b = __ldcs(&b_params4[i]);
        float4 v;
        v.x = __ldg(&Param_b[b.x]);
        v.y = __ldg(&Param_b[b.y]);
        v.z = __ldg(&Param_b[b.z]);
        v.w = __ldg(&Param_b[b.w]);
        out4[i] = v;
    }
}

// 4 edges per thread. Param_W in shared memory (removes ~half the L1tex
// gather wavefronts); occupancy pinned via launch_bounds so regs stay <= 32.
__global__ void __launch_bounds__(256, 8) edge_scatter_kernel(
        const float* __restrict__ x,
        const float* __restrict__ Param_W,
        const int4* __restrict__ w_rows4,
        const int4* __restrict__ w_cols4,
        const int4* __restrict__ w_params4,
        float* __restrict__ out, int e4, int npw) {
    extern __shared__ float s_pw[];
    for (int k = threadIdx.x; k < npw; k += blockDim.x)
        s_pw[k] = Param_W[k];
    __syncthreads();

    int i = blockIdx.x * blockDim.x + threadIdx.x;
    if (i >= e4) return;

    int4 r = __ldcs(&w_rows4[i]);
    int4 c = __ldcs(&w_cols4[i]);
    int4 p = __ldcs(&w_params4[i]);

    // x gathers first (maximize MLP before dependent atomics)
    float x0 = __ldg(&x[c.x]);
    float x1 = __ldg(&x[c.y]);
    float x2 = __ldg(&x[c.z]);
    float x3 = __ldg(&x[c.w]);
    float w0 = s_pw[p.x];
    float w1 = s_pw[p.y];
    float w2 = s_pw[p.z];
    float w3 = s_pw[p.w];

    atomicAdd(&out[r.x], w0 * x0);
    atomicAdd(&out[r.y], w1 * x1);
    atomicAdd(&out[r.z], w2 * x2);
    atomicAdd(&out[r.w], w3 * x3);
}

// Scalar fallbacks for sizes not divisible by 4 (not expected for this shape)
__global__ void bias_init_tail_kernel(const float* __restrict__ Param_b,
                                      const int* __restrict__ b_params,
                                      float* __restrict__ out, int start, int n) {
    int i = start + blockIdx.x * blockDim.x + threadIdx.x;
    if (i < n) out[i] = Param_b[b_params[i]];
}

__global__ void edge_scatter_tail_kernel(const float* __restrict__ x,
                                         const float* __restrict__ Param_W,
                                         const int* __restrict__ w_rows,
                                         const int* __restrict__ w_cols,
                                         const int* __restrict__ w_params,
                                         float* __restrict__ out,
                                         int start, int e) {
    int i = start + blockIdx.x * blockDim.x + threadIdx.x;
    if (i < e) {
        atomicAdd(&out[w_rows[i]], __ldg(&Param_W[w_params[i]]) * __ldg(&x[w_cols[i]]));
    }
}

extern "C" void kernel_launch(void* const* d_in, const int* in_sizes, int n_in,
                              void* d_out, int out_size) {
    // metadata order: x, Param_W, Param_b, w_rows, w_cols, w_params, b_params
    const float* x        = (const float*)d_in[0];
    const float* Param_W  = (const float*)d_in[1];
    const float* Param_b  = (const float*)d_in[2];
    const int*   w_rows   = (const int*)d_in[3];
    const int*   w_cols   = (const int*)d_in[4];
    const int*   w_params = (const int*)d_in[5];
    const int*   b_params = (const int*)d_in[6];
    float* out = (float*)d_out;

    int n   = out_size;       // N = 262144
    int e   = in_sizes[3];    // E = 16777216
    int npw = in_sizes[1];    // NPARAMS = 1280

    // 1) bias init (vectorized)
    int n4 = n / 4;
    if (n4 > 0) {
        int threads = 256;
        int blocks = (n4 + threads - 1) / threads;
        bias_init_kernel<<<blocks, threads>>>(Param_b, (const int4*)b_params,
                                              (float4*)out, n4);
    }
    if (n4 * 4 < n) {
        int rem = n - n4 * 4;
        bias_init_tail_kernel<<<(rem + 255) / 256, 256>>>(Param_b, b_params, out,
                                                          n4 * 4, n);
    }

    // 2) edge scatter, 4 edges per thread, Param_W in dynamic smem
    int e4 = e / 4;
    if (e4 > 0) {
        int threads = 256;
        int blocks = (e4 + threads - 1) / threads;
        size_t smem = (size_t)npw * sizeof(float);
        edge_scatter_kernel<<<blocks, threads, smem>>>(
            x, Param_W,
            (const int4*)w_rows, (const int4*)w_cols, (const int4*)w_params,
            out, e4, npw);
    }

    int tail_start = e4 * 4;
    if (tail_start < e) {
        int rem = e - tail_start;
        edge_scatter_tail_kernel<<<(rem + 255) / 256, 256>>>(
            x, Param_W, w_rows, w_cols, w_params, out, tail_start, e);
    }
}